// round 14
// baseline (speedup 1.0000x reference)
#include <cuda_runtime.h>
#include <cuda_bf16.h>
#include <cstdint>

#define NN 50000
#define NE 800000
#define NG 8
#define D  128
#define DO 64

// ---------------- scratch (device globals; no allocation allowed) ----------
__device__ float g_bufA[(size_t)NN * D];   // u = x@W1 (bf16 in low half)
__device__ float g_bufB[(size_t)NN * D];   // a1 (bf16 in low half)
__device__ int   g_indeg[NN];
__device__ int   g_outdeg[NN];
__device__ int   g_offsets[NN];
__device__ int   g_cursor[NN];
__device__ int   g_csc[NE];
__device__ float g_ns[NN];
__device__ float g_nd[NN];
__device__ float2 g_nddg[NN];              // packed {nd, gid-as-int-bits}
__device__ float g_R[(size_t)NN * NG];     // per-(node,graph) layer2+pool weight
__device__ float g_Q[NG * D];              // pooled pre-W2 vectors
__device__ float g_cnt[NG];
__device__ int   g_bsum[49];               // block sums for the scan
__device__ __nv_bfloat16 g_W1h[D * D];
__device__ __nv_bfloat16 g_W1l[D * D];

__device__ __forceinline__ uint32_t pack_bf2(float a, float b) {
    __nv_bfloat162 t = __floats2bfloat162_rn(a, b);
    return *reinterpret_cast<uint32_t*>(&t);
}

// ---------------- init: zero scratch + split W1 into hi/lo bf16 ----------
__global__ void k_init(const float* __restrict__ W1) {
    int i = blockIdx.x * blockDim.x + threadIdx.x;
    if (i < NN) { g_indeg[i] = 0; g_outdeg[i] = 0; }
    if (i < NN * NG) g_R[i] = 0.f;
    if (i < NG * D) g_Q[i] = 0.f;
    if (i < NG) g_cnt[i] = 0.f;
    if (i < D * D) {
        float w = W1[i];
        __nv_bfloat16 h = __float2bfloat16(w);
        g_W1h[i] = h;
        g_W1l[i] = __float2bfloat16(w - __bfloat162float(h));
    }
}

// ---------------- degree histogram: 4 edges/thread, int4 loads ----------
__global__ __launch_bounds__(256) void k_count(const int* __restrict__ src,
                                               const int* __restrict__ dst) {
    int e = (blockIdx.x * blockDim.x + threadIdx.x) * 4;
    if (e + 4 <= NE) {
        int4 s = *(const int4*)(src + e);
        int4 d = *(const int4*)(dst + e);
        atomicAdd(&g_outdeg[s.x], 1); atomicAdd(&g_outdeg[s.y], 1);
        atomicAdd(&g_outdeg[s.z], 1); atomicAdd(&g_outdeg[s.w], 1);
        atomicAdd(&g_indeg[d.x], 1);  atomicAdd(&g_indeg[d.y], 1);
        atomicAdd(&g_indeg[d.z], 1);  atomicAdd(&g_indeg[d.w], 1);
    } else {
        for (; e < NE; e++) {
            atomicAdd(&g_outdeg[src[e]], 1);
            atomicAdd(&g_indeg[dst[e]], 1);
        }
    }
}

// ---------------- scan phase 1: block sums of indeg + norms + cnt + pack ---
__global__ __launch_bounds__(1024) void k_scan1(const int* __restrict__ gid) {
    __shared__ int hist[NG];
    __shared__ int ws[32];
    int tid = threadIdx.x;
    if (tid < NG) hist[tid] = 0;
    __syncthreads();
    int i = blockIdx.x * 1024 + tid;
    int v = 0;
    if (i < NN) {
        v = g_indeg[i];
        float nd = rsqrtf(fmaxf((float)v, 1.f));
        g_nd[i] = nd;
        g_ns[i] = rsqrtf(fmaxf((float)g_outdeg[i], 1.f));
        int g = gid[i];
        float2 p; p.x = nd; p.y = __int_as_float(g);
        g_nddg[i] = p;
        atomicAdd_block(&hist[g], 1);
    }
    int lane = tid & 31, wid = tid >> 5;
    int r = v;
    #pragma unroll
    for (int o = 16; o > 0; o >>= 1) r += __shfl_down_sync(0xFFFFFFFFu, r, o);
    if (lane == 0) ws[wid] = r;
    __syncthreads();
    if (wid == 0) {
        r = ws[lane];
        #pragma unroll
        for (int o = 16; o > 0; o >>= 1) r += __shfl_down_sync(0xFFFFFFFFu, r, o);
        if (lane == 0) g_bsum[blockIdx.x] = r;
    }
    if (wid == 1 && lane < NG && hist[lane]) atomicAdd(&g_cnt[lane], (float)hist[lane]);
}

// ---------------- scan phase 2: per-block scan (inlines the 49-sum scan) ---
__global__ __launch_bounds__(1024) void k_scan3() {
    int tid = threadIdx.x;
    int lane = tid & 31, wid = tid >> 5;
    __shared__ int ws[32];
    __shared__ int sb_excl[49];
    __shared__ int w0tot;
    int bv = 0, bincl = 0;
    if (wid < 2) {
        bv = (tid < 49) ? g_bsum[tid] : 0;
        bincl = bv;
        #pragma unroll
        for (int o = 1; o < 32; o <<= 1) {
            int t = __shfl_up_sync(0xFFFFFFFFu, bincl, o);
            if (lane >= o) bincl += t;
        }
        if (tid == 31) w0tot = bincl;
    }
    __syncthreads();
    if (wid < 2 && tid < 49)
        sb_excl[tid] = bincl - bv + (wid == 1 ? w0tot : 0);
    int i = blockIdx.x * 1024 + tid;
    int v = (i < NN) ? g_indeg[i] : 0;
    int incl = v;
    #pragma unroll
    for (int o = 1; o < 32; o <<= 1) {
        int t = __shfl_up_sync(0xFFFFFFFFu, incl, o);
        if (lane >= o) incl += t;
    }
    if (lane == 31) ws[wid] = incl;
    __syncthreads();
    if (wid == 0) {
        int wv = ws[lane];
        int wi = wv;
        #pragma unroll
        for (int o = 1; o < 32; o <<= 1) {
            int t = __shfl_up_sync(0xFFFFFFFFu, wi, o);
            if (lane >= o) wi += t;
        }
        ws[lane] = wi - wv;
    }
    __syncthreads();
    if (i < NN) {
        int excl = sb_excl[blockIdx.x] + ws[wid] + (incl - v);
        g_offsets[i] = excl;
        g_cursor[i]  = excl;
    }
}

// ---------------- merged edge pass: CSC fill + R accumulation ----------
__global__ __launch_bounds__(256) void k_fill_edgew(const int* __restrict__ src,
                                                    const int* __restrict__ dst) {
    int e = (blockIdx.x * blockDim.x + threadIdx.x) * 4;
    if (e + 4 <= NE) {
        int4 s = *(const int4*)(src + e);
        int4 d = *(const int4*)(dst + e);
        float2 p0 = g_nddg[d.x], p1 = g_nddg[d.y];
        float2 p2 = g_nddg[d.z], p3 = g_nddg[d.w];
        int q0 = atomicAdd(&g_cursor[d.x], 1);
        int q1 = atomicAdd(&g_cursor[d.y], 1);
        int q2 = atomicAdd(&g_cursor[d.z], 1);
        int q3 = atomicAdd(&g_cursor[d.w], 1);
        g_csc[q0] = s.x; g_csc[q1] = s.y; g_csc[q2] = s.z; g_csc[q3] = s.w;
        atomicAdd(&g_R[(size_t)s.x * NG + __float_as_int(p0.y)], p0.x);
        atomicAdd(&g_R[(size_t)s.y * NG + __float_as_int(p1.y)], p1.x);
        atomicAdd(&g_R[(size_t)s.z * NG + __float_as_int(p2.y)], p2.x);
        atomicAdd(&g_R[(size_t)s.w * NG + __float_as_int(p3.y)], p3.x);
    } else {
        for (; e < NE; e++) {
            int dv = dst[e], sv = src[e];
            float2 p = g_nddg[dv];
            int pos = atomicAdd(&g_cursor[dv], 1);
            g_csc[pos] = sv;
            atomicAdd(&g_R[(size_t)sv * NG + __float_as_int(p.y)], p.x);
        }
    }
}

// ---------------- tensor-core GEMM: u = x @ W1 (NO row scale), bf16 out ---
// ns commuted out of the GEMM -> this kernel depends only on x and W1-split,
// so it forks right after k_init and overlaps the whole CSC-build chain.
#define MMA_BF16(c, a, b0_, b1_) \
    asm volatile("mma.sync.aligned.m16n8k16.row.col.f32.bf16.bf16.f32 " \
        "{%0,%1,%2,%3}, {%4,%5,%6,%7}, {%8,%9}, {%0,%1,%2,%3};" \
        : "+f"((c)[0]), "+f"((c)[1]), "+f"((c)[2]), "+f"((c)[3]) \
        : "r"((a)[0]), "r"((a)[1]), "r"((a)[2]), "r"((a)[3]), "r"(b0_), "r"(b1_))

__global__ __launch_bounds__(256, 2) void k_gemm1(const float* __restrict__ X,
                                                  __nv_bfloat16* __restrict__ Out) {
    __shared__ __nv_bfloat16 As[128 * 64];
    __shared__ __nv_bfloat16 Bh[64 * 128];
    __shared__ __nv_bfloat16 Bl[64 * 128];
    const int tid = threadIdx.x;
    const int block_row = blockIdx.x * 128;
    const int wid = tid >> 5, lane = tid & 31;
    const int wm = wid & 3, wn = wid >> 2;
    const int lr = lane & 15, lc = lane >> 4;

    float acc[2][8][4];
    #pragma unroll
    for (int i = 0; i < 2; i++)
        #pragma unroll
        for (int j = 0; j < 8; j++)
            #pragma unroll
            for (int q = 0; q < 4; q++) acc[i][j][q] = 0.f;

    uint32_t as_base = (uint32_t)__cvta_generic_to_shared(As);
    uint32_t bh_base = (uint32_t)__cvta_generic_to_shared(Bh);
    uint32_t bl_base = (uint32_t)__cvta_generic_to_shared(Bl);

    for (int kc = 0; kc < 2; kc++) {
        if (kc) __syncthreads();
        #pragma unroll
        for (int i = 0; i < 4; i++) {
            int ch = tid + i * 256;
            int r = ch >> 3, c = ch & 7;
            int cs = c ^ (r & 7);
            int grow = block_row + r;
            uint4 v = make_uint4(0u, 0u, 0u, 0u);
            if (grow < NN) {
                const float* xp = X + (size_t)grow * 128 + kc * 64 + c * 8;
                float4 p = *(const float4*)xp;
                float4 q = *(const float4*)(xp + 4);
                v.x = pack_bf2(p.x, p.y);
                v.y = pack_bf2(p.z, p.w);
                v.z = pack_bf2(q.x, q.y);
                v.w = pack_bf2(q.z, q.w);
            }
            *(uint4*)(As + r * 64 + cs * 8) = v;
        }
        #pragma unroll
        for (int i = 0; i < 4; i++) {
            int ch = tid + i * 256;
            int k = ch >> 4, c = ch & 15;
            int cs = c ^ (k & 7);
            size_t off = (size_t)(kc * 64 + k) * 128 + c * 8;
            *(uint4*)(Bh + k * 128 + cs * 8) = *(const uint4*)(g_W1h + off);
            *(uint4*)(Bl + k * 128 + cs * 8) = *(const uint4*)(g_W1l + off);
        }
        __syncthreads();

        #pragma unroll
        for (int s = 0; s < 4; s++) {
            uint32_t a[2][4];
            #pragma unroll
            for (int mi = 0; mi < 2; mi++) {
                int row = wm * 32 + mi * 16 + lr;
                int cch = (s * 2 + lc) ^ (row & 7);
                uint32_t addr = as_base + (uint32_t)(row * 128 + cch * 16);
                asm volatile("ldmatrix.sync.aligned.m8n8.x4.shared.b16 {%0,%1,%2,%3}, [%4];"
                    : "=r"(a[mi][0]), "=r"(a[mi][1]), "=r"(a[mi][2]), "=r"(a[mi][3])
                    : "r"(addr) : "memory");
            }
            int krow = s * 16 + lr;
            #pragma unroll
            for (int np = 0; np < 4; np++) {
                int nc0 = (wn * 64 + np * 16) >> 3;
                int cch = (nc0 + lc) ^ (krow & 7);
                uint32_t addrh = bh_base + (uint32_t)(krow * 256 + cch * 16);
                uint32_t b[4];
                asm volatile("ldmatrix.sync.aligned.m8n8.x4.trans.shared.b16 {%0,%1,%2,%3}, [%4];"
                    : "=r"(b[0]), "=r"(b[1]), "=r"(b[2]), "=r"(b[3])
                    : "r"(addrh) : "memory");
                MMA_BF16(acc[0][np * 2],     a[0], b[0], b[1]);
                MMA_BF16(acc[1][np * 2],     a[1], b[0], b[1]);
                MMA_BF16(acc[0][np * 2 + 1], a[0], b[2], b[3]);
                MMA_BF16(acc[1][np * 2 + 1], a[1], b[2], b[3]);
                uint32_t addrl = bl_base + (uint32_t)(krow * 256 + cch * 16);
                asm volatile("ldmatrix.sync.aligned.m8n8.x4.trans.shared.b16 {%0,%1,%2,%3}, [%4];"
                    : "=r"(b[0]), "=r"(b[1]), "=r"(b[2]), "=r"(b[3])
                    : "r"(addrl) : "memory");
                MMA_BF16(acc[0][np * 2],     a[0], b[0], b[1]);
                MMA_BF16(acc[1][np * 2],     a[1], b[0], b[1]);
                MMA_BF16(acc[0][np * 2 + 1], a[0], b[2], b[3]);
                MMA_BF16(acc[1][np * 2 + 1], a[1], b[2], b[3]);
            }
        }
    }

    // ---- epilogue: f32 acc -> bf16 ----
    const int g = lane >> 2, cq = (lane & 3) * 2;
    #pragma unroll
    for (int mi = 0; mi < 2; mi++) {
        int r0 = block_row + wm * 32 + mi * 16 + g;
        #pragma unroll
        for (int nj = 0; nj < 8; nj++) {
            int col = wn * 64 + nj * 8 + cq;
            if (r0 < NN)
                *(uint32_t*)(Out + (size_t)r0 * 128 + col) =
                    pack_bf2(acc[mi][nj][0], acc[mi][nj][1]);
            if (r0 + 8 < NN)
                *(uint32_t*)(Out + (size_t)(r0 + 8) * 128 + col) =
                    pack_bf2(acc[mi][nj][2], acc[mi][nj][3]);
        }
    }
}

// ---------------- layer-1 aggregation: a1 = relu(nd*Σ ns[s]*u[s] + b1) ----
__global__ __launch_bounds__(256) void k_agg1(const __nv_bfloat16* __restrict__ H,
                                              __nv_bfloat16* __restrict__ Out,
                                              const float* __restrict__ bias) {
    int gw = (blockIdx.x * blockDim.x + threadIdx.x) >> 5;
    if (gw >= NN) return;
    int lane = threadIdx.x & 31;
    int d = lane * 4;
    int start = g_offsets[gw], end = start + g_indeg[gw];

    float a0 = 0.f, a1 = 0.f, a2 = 0.f, a3 = 0.f;
    int e = start;
    for (; e + 8 <= end; e += 8) {
        int sid[8];
        #pragma unroll
        for (int u = 0; u < 8; u++) sid[u] = g_csc[e + u];
        uint2 r[8]; float nsv[8];
        #pragma unroll
        for (int u = 0; u < 8; u++) {
            r[u] = *(const uint2*)(H + (size_t)sid[u] * 128 + d);
            nsv[u] = g_ns[sid[u]];
        }
        #pragma unroll
        for (int u = 0; u < 8; u++) {
            float2 f0 = __bfloat1622float2(*(const __nv_bfloat162*)&r[u].x);
            float2 f1 = __bfloat1622float2(*(const __nv_bfloat162*)&r[u].y);
            a0 = fmaf(nsv[u], f0.x, a0);
            a1 = fmaf(nsv[u], f0.y, a1);
            a2 = fmaf(nsv[u], f1.x, a2);
            a3 = fmaf(nsv[u], f1.y, a3);
        }
    }
    for (; e < end; e++) {
        int sidx = g_csc[e];
        float nsv = g_ns[sidx];
        uint2 r = *(const uint2*)(H + (size_t)sidx * 128 + d);
        float2 f0 = __bfloat1622float2(*(const __nv_bfloat162*)&r.x);
        float2 f1 = __bfloat1622float2(*(const __nv_bfloat162*)&r.y);
        a0 = fmaf(nsv, f0.x, a0);
        a1 = fmaf(nsv, f0.y, a1);
        a2 = fmaf(nsv, f1.x, a2);
        a3 = fmaf(nsv, f1.y, a3);
    }
    float nd = g_nd[gw];
    float4 b = *(const float4*)(bias + d);
    float o0 = fmaxf(fmaf(a0, nd, b.x), 0.f);
    float o1 = fmaxf(fmaf(a1, nd, b.y), 0.f);
    float o2 = fmaxf(fmaf(a2, nd, b.z), 0.f);
    float o3 = fmaxf(fmaf(a3, nd, b.w), 0.f);
    uint2 o;
    o.x = pack_bf2(o0, o1);
    o.y = pack_bf2(o2, o3);
    *(uint2*)(Out + (size_t)gw * 128 + d) = o;
}

// ---------------- Q[g,:] = sum_s ns[s]*R[s,g]*a1[s,:] ----------
__global__ __launch_bounds__(256) void k_pooledW(const __nv_bfloat16* __restrict__ A1) {
    __shared__ float sred[8][NG][128];   // 32KB
    const int tid = threadIdx.x;
    const int wid = tid >> 5, lane = tid & 31;
    const int d = lane * 4;
    float acc[NG][4];
    #pragma unroll
    for (int g = 0; g < NG; g++)
        #pragma unroll
        for (int j = 0; j < 4; j++) acc[g][j] = 0.f;

    int row = blockIdx.x * 256 + wid;
    #pragma unroll 4
    for (int it = 0; it < 32; it++, row += 8) {
        if (row >= NN) break;
        float rv = (lane < NG) ? g_R[(size_t)row * NG + lane] : 0.f;
        float nsv = g_ns[row];
        uint2 rr = *(const uint2*)(A1 + (size_t)row * 128 + d);
        float2 f0 = __bfloat1622float2(*(const __nv_bfloat162*)&rr.x);
        float2 f1 = __bfloat1622float2(*(const __nv_bfloat162*)&rr.y);
        #pragma unroll
        for (int g = 0; g < NG; g++) {
            float w = __shfl_sync(0xFFFFFFFFu, rv, g) * nsv;
            acc[g][0] = fmaf(w, f0.x, acc[g][0]);
            acc[g][1] = fmaf(w, f0.y, acc[g][1]);
            acc[g][2] = fmaf(w, f1.x, acc[g][2]);
            acc[g][3] = fmaf(w, f1.y, acc[g][3]);
        }
    }
    #pragma unroll
    for (int g = 0; g < NG; g++) {
        sred[wid][g][d + 0] = acc[g][0];
        sred[wid][g][d + 1] = acc[g][1];
        sred[wid][g][d + 2] = acc[g][2];
        sred[wid][g][d + 3] = acc[g][3];
    }
    __syncthreads();
    for (int idx = tid; idx < NG * 128; idx += 256) {
        int g = idx >> 7, dd = idx & 127;
        float s = 0.f;
        #pragma unroll
        for (int w = 0; w < 8; w++) s += sred[w][g][dd];
        atomicAdd(&g_Q[g * 128 + dd], s);
    }
}

// ---------------- head: out = ((Q/cnt)@W2 + b2) @ Wl + bl ----------
__global__ __launch_bounds__(1024) void k_head(const float* __restrict__ W2,
                                               const float* __restrict__ b2,
                                               const float* __restrict__ Wl,
                                               const float* __restrict__ bl,
                                               float* __restrict__ out) {
    __shared__ float tmp[NG][D];
    int tid = threadIdx.x;
    {
        int g = tid >> 7, dd = tid & 127;
        float inv = 1.f / fmaxf(g_cnt[g], 1.f);
        float acc = b2[dd];
        #pragma unroll 8
        for (int k = 0; k < D; k++)
            acc = fmaf(g_Q[g * D + k] * inv, W2[k * D + dd], acc);
        tmp[g][dd] = acc;
    }
    __syncthreads();
    if (tid < NG * DO) {
        int g = tid >> 6, n = tid & 63;
        float acc = bl[n];
        #pragma unroll 8
        for (int k = 0; k < D; k++)
            acc = fmaf(tmp[g][k], Wl[k * DO + n], acc);
        out[g * DO + n] = acc;
    }
}

// ---------------- launch ----------
extern "C" void kernel_launch(void* const* d_in, const int* in_sizes, int n_in,
                              void* d_out, int out_size) {
    const float* x   = (const float*)d_in[0];
    const float* W1  = (const float*)d_in[1];
    const float* b1  = (const float*)d_in[2];
    const float* W2  = (const float*)d_in[3];
    const float* b2  = (const float*)d_in[4];
    const float* Wl  = (const float*)d_in[5];
    const float* bl  = (const float*)d_in[6];
    const int*   src = (const int*)d_in[7];
    const int*   dst = (const int*)d_in[8];
    const int*   gid = (const int*)d_in[9];
    float* out = (float*)d_out;

    float* bufA; cudaGetSymbolAddress((void**)&bufA, g_bufA);
    float* bufB; cudaGetSymbolAddress((void**)&bufB, g_bufB);
    __nv_bfloat16* u1 = (__nv_bfloat16*)bufA;
    __nv_bfloat16* a1 = (__nv_bfloat16*)bufB;

    // one-time side stream + events; verified before use, with serial fallback
    static cudaStream_t s_side = nullptr;
    static cudaEvent_t  s_e1 = nullptr, s_e2 = nullptr;
    static int s_ok = -1;
    if (s_ok < 0) {
        cudaError_t r1 = cudaStreamCreateWithFlags(&s_side, cudaStreamNonBlocking);
        cudaError_t r2 = cudaEventCreateWithFlags(&s_e1, cudaEventDisableTiming);
        cudaError_t r3 = cudaEventCreateWithFlags(&s_e2, cudaEventDisableTiming);
        s_ok = (r1 == cudaSuccess && r2 == cudaSuccess && r3 == cudaSuccess) ? 1 : 0;
    }

    const int eb4 = (NE / 4 + 255) / 256;   // 782 blocks, 4 edges/thread

    k_init<<<(NN * NG + 255) / 256, 256>>>(W1);              // 0

    if (s_ok == 1) {
        // fork right after init: gemm needs only x + W1-split.
        // It overlaps the ENTIRE count->scan->fill chain (~35us window).
        cudaEventRecord(s_e1, 0);
        cudaStreamWaitEvent(s_side, s_e1, 0);
        k_gemm1<<<(NN + 127) / 128, 256, 0, s_side>>>(x, u1);  // 1 (side)
        cudaEventRecord(s_e2, s_side);

        k_count<<<eb4, 256>>>(src, dst);                       // 2
        k_scan1<<<49, 1024>>>(gid);                            // 3
        k_scan3<<<49, 1024>>>();                               // 4
        k_fill_edgew<<<eb4, 256>>>(src, dst);                  // 5

        cudaStreamWaitEvent(0, s_e2, 0);
    } else {
        // serial fallback (identical semantics)
        k_gemm1<<<(NN + 127) / 128, 256>>>(x, u1);
        k_count<<<eb4, 256>>>(src, dst);
        k_scan1<<<49, 1024>>>(gid);
        k_scan3<<<49, 1024>>>();
        k_fill_edgew<<<eb4, 256>>>(src, dst);
    }

    k_agg1<<<(NN * 32 + 255) / 256, 256>>>(u1, a1, b1);      // 6
    k_pooledW<<<196, 256>>>(a1);                             // 7
    k_head<<<1, 1024>>>(W2, b2, Wl, bl, out);                // 8
}

// round 15
// speedup vs baseline: 1.0257x; 1.0257x over previous
#include <cuda_runtime.h>
#include <cuda_bf16.h>
#include <cstdint>

#define NN 50000
#define NE 800000
#define NG 8
#define D  128
#define DO 64

// ---------------- scratch (device globals; no allocation allowed) ----------
__device__ float g_bufA[(size_t)NN * D];   // u = x@W1 (bf16 in low half)
__device__ float g_bufB[(size_t)NN * D];   // a1 (bf16 in low half)
__device__ int   g_indeg[NN];
__device__ int   g_outdeg[NN];
__device__ int   g_offsets[NN];
__device__ int   g_cursor[NN];
__device__ int   g_csc[NE];
__device__ float g_ns[NN];
__device__ float g_nd[NN];
__device__ float2 g_nddg[NN];              // packed {nd, gid-as-int-bits}
__device__ float g_R[(size_t)NN * NG];     // per-(node,graph) layer2+pool weight
__device__ float g_Q[NG * D];              // pooled pre-W2 vectors
__device__ float g_cnt[NG];
__device__ int   g_bsum[49];               // block sums for the scan
__device__ __nv_bfloat16 g_W1b[D * D];     // W1 in bf16

__device__ __forceinline__ uint32_t pack_bf2(float a, float b) {
    __nv_bfloat162 t = __floats2bfloat162_rn(a, b);
    return *reinterpret_cast<uint32_t*>(&t);
}

// ---------------- init: zero scratch + W1 -> bf16 ----------
__global__ void k_init(const float* __restrict__ W1) {
    int i = blockIdx.x * blockDim.x + threadIdx.x;
    if (i < NN) { g_indeg[i] = 0; g_outdeg[i] = 0; }
    if (i < NN * NG) g_R[i] = 0.f;
    if (i < NG * D) g_Q[i] = 0.f;
    if (i < NG) g_cnt[i] = 0.f;
    if (i < D * D) g_W1b[i] = __float2bfloat16(W1[i]);
}

// ---------------- degree histogram: 4 edges/thread, int4 loads ----------
__global__ __launch_bounds__(256) void k_count(const int* __restrict__ src,
                                               const int* __restrict__ dst) {
    int e = (blockIdx.x * blockDim.x + threadIdx.x) * 4;
    if (e + 4 <= NE) {
        int4 s = *(const int4*)(src + e);
        int4 d = *(const int4*)(dst + e);
        atomicAdd(&g_outdeg[s.x], 1); atomicAdd(&g_outdeg[s.y], 1);
        atomicAdd(&g_outdeg[s.z], 1); atomicAdd(&g_outdeg[s.w], 1);
        atomicAdd(&g_indeg[d.x], 1);  atomicAdd(&g_indeg[d.y], 1);
        atomicAdd(&g_indeg[d.z], 1);  atomicAdd(&g_indeg[d.w], 1);
    } else {
        for (; e < NE; e++) {
            atomicAdd(&g_outdeg[src[e]], 1);
            atomicAdd(&g_indeg[dst[e]], 1);
        }
    }
}

// ---------------- scan phase 1: block sums of indeg + norms + cnt + pack ---
__global__ __launch_bounds__(1024) void k_scan1(const int* __restrict__ gid) {
    __shared__ int hist[NG];
    __shared__ int ws[32];
    int tid = threadIdx.x;
    if (tid < NG) hist[tid] = 0;
    __syncthreads();
    int i = blockIdx.x * 1024 + tid;
    int v = 0;
    if (i < NN) {
        v = g_indeg[i];
        float nd = rsqrtf(fmaxf((float)v, 1.f));
        g_nd[i] = nd;
        g_ns[i] = rsqrtf(fmaxf((float)g_outdeg[i], 1.f));
        int g = gid[i];
        float2 p; p.x = nd; p.y = __int_as_float(g);
        g_nddg[i] = p;
        atomicAdd_block(&hist[g], 1);
    }
    int lane = tid & 31, wid = tid >> 5;
    int r = v;
    #pragma unroll
    for (int o = 16; o > 0; o >>= 1) r += __shfl_down_sync(0xFFFFFFFFu, r, o);
    if (lane == 0) ws[wid] = r;
    __syncthreads();
    if (wid == 0) {
        r = ws[lane];
        #pragma unroll
        for (int o = 16; o > 0; o >>= 1) r += __shfl_down_sync(0xFFFFFFFFu, r, o);
        if (lane == 0) g_bsum[blockIdx.x] = r;
    }
    if (wid == 1 && lane < NG && hist[lane]) atomicAdd(&g_cnt[lane], (float)hist[lane]);
}

// ---------------- scan phase 2: per-block scan (inlines the 49-sum scan) ---
__global__ __launch_bounds__(1024) void k_scan3() {
    int tid = threadIdx.x;
    int lane = tid & 31, wid = tid >> 5;
    __shared__ int ws[32];
    __shared__ int sb_excl[49];
    __shared__ int w0tot;
    int bv = 0, bincl = 0;
    if (wid < 2) {
        bv = (tid < 49) ? g_bsum[tid] : 0;
        bincl = bv;
        #pragma unroll
        for (int o = 1; o < 32; o <<= 1) {
            int t = __shfl_up_sync(0xFFFFFFFFu, bincl, o);
            if (lane >= o) bincl += t;
        }
        if (tid == 31) w0tot = bincl;
    }
    __syncthreads();
    if (wid < 2 && tid < 49)
        sb_excl[tid] = bincl - bv + (wid == 1 ? w0tot : 0);
    int i = blockIdx.x * 1024 + tid;
    int v = (i < NN) ? g_indeg[i] : 0;
    int incl = v;
    #pragma unroll
    for (int o = 1; o < 32; o <<= 1) {
        int t = __shfl_up_sync(0xFFFFFFFFu, incl, o);
        if (lane >= o) incl += t;
    }
    if (lane == 31) ws[wid] = incl;
    __syncthreads();
    if (wid == 0) {
        int wv = ws[lane];
        int wi = wv;
        #pragma unroll
        for (int o = 1; o < 32; o <<= 1) {
            int t = __shfl_up_sync(0xFFFFFFFFu, wi, o);
            if (lane >= o) wi += t;
        }
        ws[lane] = wi - wv;
    }
    __syncthreads();
    if (i < NN) {
        int excl = sb_excl[blockIdx.x] + ws[wid] + (incl - v);
        g_offsets[i] = excl;
        g_cursor[i]  = excl;
    }
}

// ---------------- merged edge pass: CSC fill + R accumulation ----------
__global__ __launch_bounds__(256) void k_fill_edgew(const int* __restrict__ src,
                                                    const int* __restrict__ dst) {
    int e = (blockIdx.x * blockDim.x + threadIdx.x) * 4;
    if (e + 4 <= NE) {
        int4 s = *(const int4*)(src + e);
        int4 d = *(const int4*)(dst + e);
        float2 p0 = g_nddg[d.x], p1 = g_nddg[d.y];
        float2 p2 = g_nddg[d.z], p3 = g_nddg[d.w];
        int q0 = atomicAdd(&g_cursor[d.x], 1);
        int q1 = atomicAdd(&g_cursor[d.y], 1);
        int q2 = atomicAdd(&g_cursor[d.z], 1);
        int q3 = atomicAdd(&g_cursor[d.w], 1);
        g_csc[q0] = s.x; g_csc[q1] = s.y; g_csc[q2] = s.z; g_csc[q3] = s.w;
        atomicAdd(&g_R[(size_t)s.x * NG + __float_as_int(p0.y)], p0.x);
        atomicAdd(&g_R[(size_t)s.y * NG + __float_as_int(p1.y)], p1.x);
        atomicAdd(&g_R[(size_t)s.z * NG + __float_as_int(p2.y)], p2.x);
        atomicAdd(&g_R[(size_t)s.w * NG + __float_as_int(p3.y)], p3.x);
    } else {
        for (; e < NE; e++) {
            int dv = dst[e], sv = src[e];
            float2 p = g_nddg[dv];
            int pos = atomicAdd(&g_cursor[dv], 1);
            g_csc[pos] = sv;
            atomicAdd(&g_R[(size_t)sv * NG + __float_as_int(p.y)], p.x);
        }
    }
}

// ---------------- tensor-core GEMM: u = x @ W1 (single bf16 W), bf16 out --
#define MMA_BF16(c, a, b0_, b1_) \
    asm volatile("mma.sync.aligned.m16n8k16.row.col.f32.bf16.bf16.f32 " \
        "{%0,%1,%2,%3}, {%4,%5,%6,%7}, {%8,%9}, {%0,%1,%2,%3};" \
        : "+f"((c)[0]), "+f"((c)[1]), "+f"((c)[2]), "+f"((c)[3]) \
        : "r"((a)[0]), "r"((a)[1]), "r"((a)[2]), "r"((a)[3]), "r"(b0_), "r"(b1_))

__global__ __launch_bounds__(256, 2) void k_gemm1(const float* __restrict__ X,
                                                  __nv_bfloat16* __restrict__ Out) {
    __shared__ __nv_bfloat16 As[128 * 64];
    __shared__ __nv_bfloat16 Bh[64 * 128];
    const int tid = threadIdx.x;
    const int block_row = blockIdx.x * 128;
    const int wid = tid >> 5, lane = tid & 31;
    const int wm = wid & 3, wn = wid >> 2;
    const int lr = lane & 15, lc = lane >> 4;

    float acc[2][8][4];
    #pragma unroll
    for (int i = 0; i < 2; i++)
        #pragma unroll
        for (int j = 0; j < 8; j++)
            #pragma unroll
            for (int q = 0; q < 4; q++) acc[i][j][q] = 0.f;

    uint32_t as_base = (uint32_t)__cvta_generic_to_shared(As);
    uint32_t bh_base = (uint32_t)__cvta_generic_to_shared(Bh);

    for (int kc = 0; kc < 2; kc++) {
        if (kc) __syncthreads();
        #pragma unroll
        for (int i = 0; i < 4; i++) {
            int ch = tid + i * 256;
            int r = ch >> 3, c = ch & 7;
            int cs = c ^ (r & 7);
            int grow = block_row + r;
            uint4 v = make_uint4(0u, 0u, 0u, 0u);
            if (grow < NN) {
                const float* xp = X + (size_t)grow * 128 + kc * 64 + c * 8;
                float4 p = *(const float4*)xp;
                float4 q = *(const float4*)(xp + 4);
                v.x = pack_bf2(p.x, p.y);
                v.y = pack_bf2(p.z, p.w);
                v.z = pack_bf2(q.x, q.y);
                v.w = pack_bf2(q.z, q.w);
            }
            *(uint4*)(As + r * 64 + cs * 8) = v;
        }
        #pragma unroll
        for (int i = 0; i < 4; i++) {
            int ch = tid + i * 256;
            int k = ch >> 4, c = ch & 15;
            int cs = c ^ (k & 7);
            size_t off = (size_t)(kc * 64 + k) * 128 + c * 8;
            *(uint4*)(Bh + k * 128 + cs * 8) = *(const uint4*)(g_W1b + off);
        }
        __syncthreads();

        #pragma unroll
        for (int s = 0; s < 4; s++) {
            uint32_t a[2][4];
            #pragma unroll
            for (int mi = 0; mi < 2; mi++) {
                int row = wm * 32 + mi * 16 + lr;
                int cch = (s * 2 + lc) ^ (row & 7);
                uint32_t addr = as_base + (uint32_t)(row * 128 + cch * 16);
                asm volatile("ldmatrix.sync.aligned.m8n8.x4.shared.b16 {%0,%1,%2,%3}, [%4];"
                    : "=r"(a[mi][0]), "=r"(a[mi][1]), "=r"(a[mi][2]), "=r"(a[mi][3])
                    : "r"(addr) : "memory");
            }
            int krow = s * 16 + lr;
            #pragma unroll
            for (int np = 0; np < 4; np++) {
                int nc0 = (wn * 64 + np * 16) >> 3;
                int cch = (nc0 + lc) ^ (krow & 7);
                uint32_t addrh = bh_base + (uint32_t)(krow * 256 + cch * 16);
                uint32_t b[4];
                asm volatile("ldmatrix.sync.aligned.m8n8.x4.trans.shared.b16 {%0,%1,%2,%3}, [%4];"
                    : "=r"(b[0]), "=r"(b[1]), "=r"(b[2]), "=r"(b[3])
                    : "r"(addrh) : "memory");
                MMA_BF16(acc[0][np * 2],     a[0], b[0], b[1]);
                MMA_BF16(acc[1][np * 2],     a[1], b[0], b[1]);
                MMA_BF16(acc[0][np * 2 + 1], a[0], b[2], b[3]);
                MMA_BF16(acc[1][np * 2 + 1], a[1], b[2], b[3]);
            }
        }
    }

    // ---- epilogue: f32 acc -> bf16 ----
    const int g = lane >> 2, cq = (lane & 3) * 2;
    #pragma unroll
    for (int mi = 0; mi < 2; mi++) {
        int r0 = block_row + wm * 32 + mi * 16 + g;
        #pragma unroll
        for (int nj = 0; nj < 8; nj++) {
            int col = wn * 64 + nj * 8 + cq;
            if (r0 < NN)
                *(uint32_t*)(Out + (size_t)r0 * 128 + col) =
                    pack_bf2(acc[mi][nj][0], acc[mi][nj][1]);
            if (r0 + 8 < NN)
                *(uint32_t*)(Out + (size_t)(r0 + 8) * 128 + col) =
                    pack_bf2(acc[mi][nj][2], acc[mi][nj][3]);
        }
    }
}

// ---------------- layer-1 aggregation: a1 = relu(nd*Σ ns[s]*u[s] + b1) ----
__global__ __launch_bounds__(256) void k_agg1(const __nv_bfloat16* __restrict__ H,
                                              __nv_bfloat16* __restrict__ Out,
                                              const float* __restrict__ bias) {
    int gw = (blockIdx.x * blockDim.x + threadIdx.x) >> 5;
    if (gw >= NN) return;
    int lane = threadIdx.x & 31;
    int d = lane * 4;
    int start = g_offsets[gw], end = start + g_indeg[gw];

    float a0 = 0.f, a1 = 0.f, a2 = 0.f, a3 = 0.f;
    int e = start;
    for (; e + 8 <= end; e += 8) {
        int sid[8];
        #pragma unroll
        for (int u = 0; u < 8; u++) sid[u] = g_csc[e + u];
        uint2 r[8]; float nsv[8];
        #pragma unroll
        for (int u = 0; u < 8; u++) {
            r[u] = *(const uint2*)(H + (size_t)sid[u] * 128 + d);
            nsv[u] = g_ns[sid[u]];
        }
        #pragma unroll
        for (int u = 0; u < 8; u++) {
            float2 f0 = __bfloat1622float2(*(const __nv_bfloat162*)&r[u].x);
            float2 f1 = __bfloat1622float2(*(const __nv_bfloat162*)&r[u].y);
            a0 = fmaf(nsv[u], f0.x, a0);
            a1 = fmaf(nsv[u], f0.y, a1);
            a2 = fmaf(nsv[u], f1.x, a2);
            a3 = fmaf(nsv[u], f1.y, a3);
        }
    }
    for (; e < end; e++) {
        int sidx = g_csc[e];
        float nsv = g_ns[sidx];
        uint2 r = *(const uint2*)(H + (size_t)sidx * 128 + d);
        float2 f0 = __bfloat1622float2(*(const __nv_bfloat162*)&r.x);
        float2 f1 = __bfloat1622float2(*(const __nv_bfloat162*)&r.y);
        a0 = fmaf(nsv, f0.x, a0);
        a1 = fmaf(nsv, f0.y, a1);
        a2 = fmaf(nsv, f1.x, a2);
        a3 = fmaf(nsv, f1.y, a3);
    }
    float nd = g_nd[gw];
    float4 b = *(const float4*)(bias + d);
    float o0 = fmaxf(fmaf(a0, nd, b.x), 0.f);
    float o1 = fmaxf(fmaf(a1, nd, b.y), 0.f);
    float o2 = fmaxf(fmaf(a2, nd, b.z), 0.f);
    float o3 = fmaxf(fmaf(a3, nd, b.w), 0.f);
    uint2 o;
    o.x = pack_bf2(o0, o1);
    o.y = pack_bf2(o2, o3);
    *(uint2*)(Out + (size_t)gw * 128 + d) = o;
}

// ---------------- Q[g,:] = sum_s ns[s]*R[s,g]*a1[s,:] ----------
__global__ __launch_bounds__(256) void k_pooledW(const __nv_bfloat16* __restrict__ A1) {
    __shared__ float sred[8][NG][128];   // 32KB
    const int tid = threadIdx.x;
    const int wid = tid >> 5, lane = tid & 31;
    const int d = lane * 4;
    float acc[NG][4];
    #pragma unroll
    for (int g = 0; g < NG; g++)
        #pragma unroll
        for (int j = 0; j < 4; j++) acc[g][j] = 0.f;

    int row = blockIdx.x * 256 + wid;
    #pragma unroll 4
    for (int it = 0; it < 32; it++, row += 8) {
        if (row >= NN) break;
        float rv = (lane < NG) ? g_R[(size_t)row * NG + lane] : 0.f;
        float nsv = g_ns[row];
        uint2 rr = *(const uint2*)(A1 + (size_t)row * 128 + d);
        float2 f0 = __bfloat1622float2(*(const __nv_bfloat162*)&rr.x);
        float2 f1 = __bfloat1622float2(*(const __nv_bfloat162*)&rr.y);
        #pragma unroll
        for (int g = 0; g < NG; g++) {
            float w = __shfl_sync(0xFFFFFFFFu, rv, g) * nsv;
            acc[g][0] = fmaf(w, f0.x, acc[g][0]);
            acc[g][1] = fmaf(w, f0.y, acc[g][1]);
            acc[g][2] = fmaf(w, f1.x, acc[g][2]);
            acc[g][3] = fmaf(w, f1.y, acc[g][3]);
        }
    }
    #pragma unroll
    for (int g = 0; g < NG; g++) {
        sred[wid][g][d + 0] = acc[g][0];
        sred[wid][g][d + 1] = acc[g][1];
        sred[wid][g][d + 2] = acc[g][2];
        sred[wid][g][d + 3] = acc[g][3];
    }
    __syncthreads();
    for (int idx = tid; idx < NG * 128; idx += 256) {
        int g = idx >> 7, dd = idx & 127;
        float s = 0.f;
        #pragma unroll
        for (int w = 0; w < 8; w++) s += sred[w][g][dd];
        atomicAdd(&g_Q[g * 128 + dd], s);
    }
}

// ---------------- head: out = ((Q/cnt)@W2 + b2) @ Wl + bl ----------
__global__ __launch_bounds__(1024) void k_head(const float* __restrict__ W2,
                                               const float* __restrict__ b2,
                                               const float* __restrict__ Wl,
                                               const float* __restrict__ bl,
                                               float* __restrict__ out) {
    __shared__ float tmp[NG][D];
    int tid = threadIdx.x;
    {
        int g = tid >> 7, dd = tid & 127;
        float inv = 1.f / fmaxf(g_cnt[g], 1.f);
        float acc = b2[dd];
        #pragma unroll 8
        for (int k = 0; k < D; k++)
            acc = fmaf(g_Q[g * D + k] * inv, W2[k * D + dd], acc);
        tmp[g][dd] = acc;
    }
    __syncthreads();
    if (tid < NG * DO) {
        int g = tid >> 6, n = tid & 63;
        float acc = bl[n];
        #pragma unroll 8
        for (int k = 0; k < D; k++)
            acc = fmaf(tmp[g][k], Wl[k * DO + n], acc);
        out[g * DO + n] = acc;
    }
}

// ---------------- launch ----------
extern "C" void kernel_launch(void* const* d_in, const int* in_sizes, int n_in,
                              void* d_out, int out_size) {
    const float* x   = (const float*)d_in[0];
    const float* W1  = (const float*)d_in[1];
    const float* b1  = (const float*)d_in[2];
    const float* W2  = (const float*)d_in[3];
    const float* b2  = (const float*)d_in[4];
    const float* Wl  = (const float*)d_in[5];
    const float* bl  = (const float*)d_in[6];
    const int*   src = (const int*)d_in[7];
    const int*   dst = (const int*)d_in[8];
    const int*   gid = (const int*)d_in[9];
    float* out = (float*)d_out;

    float* bufA; cudaGetSymbolAddress((void**)&bufA, g_bufA);
    float* bufB; cudaGetSymbolAddress((void**)&bufB, g_bufB);
    __nv_bfloat16* u1 = (__nv_bfloat16*)bufA;
    __nv_bfloat16* a1 = (__nv_bfloat16*)bufB;

    // one-time side stream + events; verified before use, with serial fallback
    static cudaStream_t s_side = nullptr;
    static cudaEvent_t  s_e1 = nullptr, s_e2 = nullptr;
    static int s_ok = -1;
    if (s_ok < 0) {
        cudaError_t r1 = cudaStreamCreateWithFlags(&s_side, cudaStreamNonBlocking);
        cudaError_t r2 = cudaEventCreateWithFlags(&s_e1, cudaEventDisableTiming);
        cudaError_t r3 = cudaEventCreateWithFlags(&s_e2, cudaEventDisableTiming);
        s_ok = (r1 == cudaSuccess && r2 == cudaSuccess && r3 == cudaSuccess) ? 1 : 0;
    }

    const int eb4 = (NE / 4 + 255) / 256;   // 782 blocks, 4 edges/thread

    k_init<<<(NN * NG + 255) / 256, 256>>>(W1);              // 0

    if (s_ok == 1) {
        cudaEventRecord(s_e1, 0);
        cudaStreamWaitEvent(s_side, s_e1, 0);
        k_gemm1<<<(NN + 127) / 128, 256, 0, s_side>>>(x, u1);  // 1 (side)
        cudaEventRecord(s_e2, s_side);

        k_count<<<eb4, 256>>>(src, dst);                       // 2
        k_scan1<<<49, 1024>>>(gid);                            // 3
        k_scan3<<<49, 1024>>>();                               // 4
        k_fill_edgew<<<eb4, 256>>>(src, dst);                  // 5

        cudaStreamWaitEvent(0, s_e2, 0);
    } else {
        k_gemm1<<<(NN + 127) / 128, 256>>>(x, u1);
        k_count<<<eb4, 256>>>(src, dst);
        k_scan1<<<49, 1024>>>(gid);
        k_scan3<<<49, 1024>>>();
        k_fill_edgew<<<eb4, 256>>>(src, dst);
    }

    k_agg1<<<(NN * 32 + 255) / 256, 256>>>(u1, a1, b1);      // 6
    k_pooledW<<<196, 256>>>(a1);                             // 7
    k_head<<<1, 1024>>>(W2, b2, Wl, bl, out);                // 8
}